// round 11
// baseline (speedup 1.0000x reference)
#include <cuda_runtime.h>
#include <cstdint>

#define BB 4
#define TT 256
#define LL 216
#define EPC 12
#define EROOT 12
#define EQUAL 16
#define KK 41
#define W_NM 0.1f
#define W_ADV 0.001f

// device scratch (no cudaMalloc allowed)
__device__ __align__(16) float g_Dhi[BB][TT + 1][LL];  // D = cs @ h, compensated hi
__device__ __align__(16) float g_Dlo[BB][TT + 1][LL];  // compensation (lo) part

// ---------------- fused prelude: one block per (t, b) computes D[b,t,:] ----------------
// Phase A: stage harmony arrays coalesced into smem; compute cs[t,k] = sum_{tau<t} x[tau,k]
//          with 41k x 6 tau-group threads (inputs are 1.1 MB -> L2-resident).
// Phase B: thread l folds h coefficients from smem (LDS, no strided-global fan-out)
//          and does the compensated 41-term dot -> Dhi/Dlo.
__global__ __launch_bounds__(256)
void dprep_kernel(const float* __restrict__ apc,
                  const float* __restrict__ aroot,
                  const float* __restrict__ aqual,
                  const float* __restrict__ iroot,
                  const float* __restrict__ iqual,
                  const float* __restrict__ hpc,
                  const float* __restrict__ hroot,
                  const float* __restrict__ hqual,
                  const int* __restrict__ pc_only) {
    __shared__ float sh_pc[LL * EPC];     // 2592
    __shared__ float sh_root[LL * EROOT]; // 2592
    __shared__ float sh_qual[LL * EQUAL]; // 3456
    __shared__ float part[KK][6];
    __shared__ float cs_s[KK];

    const int t   = blockIdx.x;   // 0..256 ; D row t uses sum over tau < t
    const int b   = blockIdx.y;
    const int tid = threadIdx.x;

    // stage h arrays (coalesced)
    for (int i = tid; i < LL * EPC; i += 256) sh_pc[i] = hpc[b * LL * EPC + i];
    for (int i = tid; i < LL * EROOT; i += 256) sh_root[i] = hroot[b * LL * EROOT + i];
    for (int i = tid; i < LL * EQUAL; i += 256) sh_qual[i] = hqual[b * LL * EQUAL + i];

    // cs partial sums: tid -> (k = tid%41, g = tid/41), 6 groups
    {
        int k = tid % KK;
        int g = tid / KK;
        if (g < 6) {
            float p = 0.0f;
            if (k < 40) {
                int tau = g;
                #pragma unroll 4
                for (; tau < t; tau += 6) {
                    float x;
                    if (k < 12) {
                        x = apc[(b * TT + tau) * EPC + k];
                    } else if (k < 24) {
                        int j = k - 12;
                        x = aroot[(b * TT + tau) * EROOT + j]
                          - W_ADV * iroot[(b * TT + tau) * EROOT + j];
                    } else {
                        int j = k - 24;
                        x = aqual[(b * TT + tau) * EQUAL + j]
                          - W_ADV * iqual[(b * TT + tau) * EQUAL + j];
                    }
                    p += x;
                }
            }
            part[k][g] = p;
        }
    }
    __syncthreads();
    if (tid < KK) {
        float s = (tid == 40) ? (float)t   // channel 40: sum of ones == t
                : part[tid][0] + part[tid][1] + part[tid][2]
                + part[tid][3] + part[tid][4] + part[tid][5];
        cs_s[tid] = s;
    }
    __syncthreads();

    const int l = tid;
    if (l >= LL) return;
    const int po = pc_only ? pc_only[0] : 0;

    // fold coefficients on the fly (all reads from smem)
    float hs = 0.0f;
    #pragma unroll
    for (int j = 0; j < 12; j++) hs += sh_pc[l * EPC + j];
    const float coef = (1.0f + 2.0f * W_NM) - W_ADV / hs;

    float s = 0.0f, c = 0.0f;
    #pragma unroll
    for (int k = 0; k < KK; k++) {
        float hv;
        if (k < 12)      hv = fmaf(sh_pc[l * EPC + k], coef, -W_NM);
        else if (k < 24) hv = po ? 0.0f : sh_root[l * EROOT + (k - 12)];
        else if (k < 40) hv = po ? 0.0f : sh_qual[l * EQUAL + (k - 24)];
        else             hv = -W_NM * hs;
        float a  = cs_s[k];
        float p  = a * hv;
        float ep = fmaf(a, hv, -p);      // exact product error
        float t2 = s + p;                // TwoSum
        float z  = t2 - s;
        float e2 = (s - (t2 - z)) + (p - z);
        s = t2;
        c += ep + e2;
    }
    g_Dhi[b][t][l] = s;
    g_Dlo[b][t][l] = c;
}

// ---------------- main: out[b,s,e,l] = (D[e+1,l]-D[s,l]) * inv_len, store-bound ----------------
// EXACT R6 configuration (occ=2): tile = 8 s x 32 e x full L; 256 threads
// thread: chunk c=tid&63 (c<54 active), e-group g=tid>>6
// grid: x = st (32) fastest so consecutive CTAs share the 32 staged E-rows in L2
// smem floats: hiS[8*216] | loS[8*216] | hiE[32*216] | loE[32*216] | inv[256]
#define SM_LOS 1728
#define SM_HIE 3456
#define SM_LOE 10368
#define SM_INV 17280
#define SM_FLOATS 17536   // 70144 bytes

__global__ __launch_bounds__(256, 2)
void main_kernel(float* __restrict__ out) {
    extern __shared__ float sm[];
    const int tid = threadIdx.x;
    const int st = blockIdx.x, et = blockIdx.y, b = blockIdx.z;
    const int s0 = st * 8, e0 = et * 32;

    const float* __restrict__ Dhi = &g_Dhi[b][0][0];
    const float* __restrict__ Dlo = &g_Dlo[b][0][0];

    // stage 40 D-rows (8 s-rows, 32 e-rows at t=e+1) as hi/lo
    for (int idx = tid; idx < 40 * 54; idx += 256) {
        int row = idx / 54, c = idx - row * 54;
        int t = (row < 8) ? (s0 + row) : (e0 + (row - 8) + 1);
        float4 vh = *(const float4*)(Dhi + t * LL + c * 4);
        float4 vl = *(const float4*)(Dlo + t * LL + c * 4);
        int dh = (row < 8) ? (row * LL) : (SM_HIE + (row - 8) * LL);
        int dl = dh + ((row < 8) ? SM_LOS : (SM_LOE - SM_HIE));
        *(float4*)(sm + dh + c * 4) = vh;
        *(float4*)(sm + dl + c * 4) = vl;
    }
    // inv table with validity baked in (inv = 0 for e < s)
    {
        int s = tid >> 5, e = tid & 31;
        int len = (e0 + e) - (s0 + s) + 1;
        sm[SM_INV + tid] = (len >= 1) ? __fdividef(1.0f, (float)len) : 0.0f;
    }
    __syncthreads();

    const int c = tid & 63;
    const int g = tid >> 6;
    if (c >= 54) return;

    const float4* __restrict__ hiS4 = (const float4*)sm;
    const float4* __restrict__ loS4 = (const float4*)(sm + SM_LOS);
    const float4* __restrict__ hiE4 = (const float4*)(sm + SM_HIE);
    const float4* __restrict__ loE4 = (const float4*)(sm + SM_LOE);
    const float*  __restrict__ invt = sm + SM_INV;

    float* base = out + ((size_t)(b * 65536 + s0 * 256 + e0 + g * 8)) * LL + c * 4;

    #pragma unroll 1
    for (int s = 0; s < 8; s++) {
        float4 hs = hiS4[s * 54 + c];
        float4 ls = loS4[s * 54 + c];
        float* ps = base + (size_t)s * (256 * LL);
        #pragma unroll
        for (int eg = 0; eg < 8; eg++) {
            int e = g * 8 + eg;
            float inv = invt[s * 32 + e];
            float4 he = hiE4[e * 54 + c];
            float4 le = loE4[e * 54 + c];
            float4 v;
            v.x = ((he.x - hs.x) + (le.x - ls.x)) * inv;
            v.y = ((he.y - hs.y) + (le.y - ls.y)) * inv;
            v.z = ((he.z - hs.z) + (le.z - ls.z)) * inv;
            v.w = ((he.w - hs.w) + (le.w - ls.w)) * inv;
            __stcs((float4*)(ps + eg * LL), v);   // streaming store: write-once output
        }
    }
}

extern "C" void kernel_launch(void* const* d_in, const int* in_sizes, int n_in,
                              void* d_out, int out_size) {
    const float* apc   = (const float*)d_in[0];
    const float* aroot = (const float*)d_in[1];
    const float* aqual = (const float*)d_in[2];
    // d_in[3] = inactive_pc: unused by the reference
    const float* iroot = (const float*)d_in[4];
    const float* iqual = (const float*)d_in[5];
    const float* hpc   = (const float*)d_in[6];
    const float* hroot = (const float*)d_in[7];
    const float* hqual = (const float*)d_in[8];
    const int*   pco   = (n_in > 9) ? (const int*)d_in[9] : nullptr;

    static bool attr_done = false;
    if (!attr_done) {
        cudaFuncSetAttribute(main_kernel, cudaFuncAttributeMaxDynamicSharedMemorySize,
                             SM_FLOATS * 4);
        attr_done = true;
    }

    dprep_kernel<<<dim3(TT + 1, BB), 256>>>(apc, aroot, aqual, iroot, iqual,
                                            hpc, hroot, hqual, pco);
    main_kernel<<<dim3(32, 8, BB), 256, SM_FLOATS * 4>>>((float*)d_out);
}

// round 12
// speedup vs baseline: 1.2872x; 1.2872x over previous
#include <cuda_runtime.h>
#include <cstdint>

#define BB 4
#define TT 256
#define LL 216
#define EPC 12
#define EROOT 12
#define EQUAL 16
#define KK 41
#define W_NM 0.1f
#define W_ADV 0.001f

// device scratch (no cudaMalloc allowed)
__device__ float g_cs[BB][TT + 1][48];                 // prefix sums, channel-innermost
__device__ float g_h[BB][KK][LL];                      // folded harmony coefficients, k-major
__device__ __align__(16) float g_Dhi[BB][TT + 1][LL];  // D = cs @ h, compensated hi
__device__ __align__(16) float g_Dlo[BB][TT + 1][LL];  // compensation (lo) part

// ---------------- K0: scans (blocks 0..163) + coalesced h-fold (blocks 164..167) ----------------
__global__ void prep_kernel(const float* __restrict__ apc,
                            const float* __restrict__ aroot,
                            const float* __restrict__ aqual,
                            const float* __restrict__ iroot,
                            const float* __restrict__ iqual,
                            const float* __restrict__ hpc,
                            const float* __restrict__ hroot,
                            const float* __restrict__ hqual,
                            const int* __restrict__ pc_only) {
    int bx = blockIdx.x;
    if (bx < KK * BB) {
        __shared__ float wsum[8];
        int ch = bx % KK;
        int b  = bx / KK;
        int t  = threadIdx.x;
        int w  = t >> 5, lane = t & 31;
        float x;
        if (ch < 12) {
            x = apc[(b * TT + t) * EPC + ch];
        } else if (ch < 24) {
            int j = ch - 12;
            x = aroot[(b * TT + t) * EROOT + j] - W_ADV * iroot[(b * TT + t) * EROOT + j];
        } else if (ch < 40) {
            int j = ch - 24;
            x = aqual[(b * TT + t) * EQUAL + j] - W_ADV * iqual[(b * TT + t) * EQUAL + j];
        } else {
            x = 1.0f;  // channel 40 carries the -W_NM*Hs term (segment mean == 1)
        }
        float v = x;
        #pragma unroll
        for (int off = 1; off < 32; off <<= 1) {
            float n = __shfl_up_sync(0xFFFFFFFFu, v, off);
            if (lane >= off) v += n;
        }
        if (lane == 31) wsum[w] = v;
        __syncthreads();
        if (t < 8) {
            float s = wsum[t];
            #pragma unroll
            for (int off = 1; off < 8; off <<= 1) {
                float n = __shfl_up_sync(0x000000FFu, s, off);
                if (t >= off) s += n;
            }
            wsum[t] = s;
        }
        __syncthreads();
        float base = (w > 0) ? wsum[w - 1] : 0.0f;
        g_cs[b][t + 1][ch] = v + base;
        if (t == 0) g_cs[b][0][ch] = 0.0f;
    } else {
        // h-fold for batch b: stage inputs coalesced, fold from smem, store coalesced
        __shared__ float sh_pc[LL * EPC];
        __shared__ float sh_root[LL * EROOT];
        __shared__ float sh_qual[LL * EQUAL];
        int b = bx - KK * BB;
        int tid = threadIdx.x;
        for (int i = tid; i < LL * EPC; i += 256) sh_pc[i] = hpc[b * LL * EPC + i];
        for (int i = tid; i < LL * EROOT; i += 256) sh_root[i] = hroot[b * LL * EROOT + i];
        for (int i = tid; i < LL * EQUAL; i += 256) sh_qual[i] = hqual[b * LL * EQUAL + i];
        __syncthreads();
        int l = tid;
        if (l >= LL) return;
        int po = pc_only ? pc_only[0] : 0;
        float hs = 0.0f;
        #pragma unroll
        for (int j = 0; j < 12; j++) hs += sh_pc[l * EPC + j];
        float coef = (1.0f + 2.0f * W_NM) - W_ADV / hs;
        #pragma unroll
        for (int j = 0; j < 12; j++) g_h[b][j][l] = fmaf(sh_pc[l * EPC + j], coef, -W_NM);
        #pragma unroll
        for (int j = 0; j < 12; j++) g_h[b][12 + j][l] = po ? 0.0f : sh_root[l * EROOT + j];
        #pragma unroll
        for (int j = 0; j < 16; j++) g_h[b][24 + j][l] = po ? 0.0f : sh_qual[l * EQUAL + j];
        g_h[b][40][l] = -W_NM * hs;
    }
}

// ---------------- K1: D = cs @ h (g_h coalesced), fp32 compensated accumulation ----------------
__global__ __launch_bounds__(224)
void d_kernel() {
    __shared__ float cs_s[KK];
    int t = blockIdx.x;   // 0..256
    int b = blockIdx.y;
    int l = threadIdx.x;  // 0..223
    if (l < KK) cs_s[l] = g_cs[b][t][l];
    __syncthreads();
    if (l >= LL) return;

    float s = 0.0f, c = 0.0f;
    #pragma unroll
    for (int k = 0; k < KK; k++) {
        float a  = cs_s[k];
        float h  = g_h[b][k][l];
        float p  = a * h;
        float ep = fmaf(a, h, -p);       // exact product error
        float tt = s + p;                // TwoSum
        float z  = tt - s;
        float e2 = (s - (tt - z)) + (p - z);
        s = tt;
        c += ep + e2;
    }
    g_Dhi[b][t][l] = s;
    g_Dlo[b][t][l] = c;
}

// ---------------- main: out[b,s,e,l] = (D[e+1,l]-D[s,l]) * inv_len ----------------
// R6 tile shape, but E hi/lo register-blocked: each thread loads its 8 E float4 pairs ONCE,
// then loops s. LDS traffic drops ~4x (L1tex was the binding resource at 73.9%).
// smem floats: hiS[8*216] | loS[8*216] | hiE[32*216] | loE[32*216] | inv[256]
#define SM_LOS 1728
#define SM_HIE 3456
#define SM_LOE 10368
#define SM_INV 17280
#define SM_FLOATS 17536   // 70144 bytes

__global__ __launch_bounds__(256, 2)
void main_kernel(float* __restrict__ out) {
    extern __shared__ float sm[];
    const int tid = threadIdx.x;
    const int st = blockIdx.x, et = blockIdx.y, b = blockIdx.z;
    const int s0 = st * 8, e0 = et * 32;

    const float* __restrict__ Dhi = &g_Dhi[b][0][0];
    const float* __restrict__ Dlo = &g_Dlo[b][0][0];

    // stage 40 D-rows (8 s-rows, 32 e-rows at t=e+1) as hi/lo
    for (int idx = tid; idx < 40 * 54; idx += 256) {
        int row = idx / 54, c = idx - row * 54;
        int t = (row < 8) ? (s0 + row) : (e0 + (row - 8) + 1);
        float4 vh = *(const float4*)(Dhi + t * LL + c * 4);
        float4 vl = *(const float4*)(Dlo + t * LL + c * 4);
        int dh = (row < 8) ? (row * LL) : (SM_HIE + (row - 8) * LL);
        int dl = dh + ((row < 8) ? SM_LOS : (SM_LOE - SM_HIE));
        *(float4*)(sm + dh + c * 4) = vh;
        *(float4*)(sm + dl + c * 4) = vl;
    }
    // inv table with validity baked in (inv = 0 for e < s)
    {
        int s = tid >> 5, e = tid & 31;
        int len = (e0 + e) - (s0 + s) + 1;
        sm[SM_INV + tid] = (len >= 1) ? __fdividef(1.0f, (float)len) : 0.0f;
    }
    __syncthreads();

    const int c = tid & 63;
    const int g = tid >> 6;
    if (c >= 54) return;

    const float4* __restrict__ hiS4 = (const float4*)sm;
    const float4* __restrict__ loS4 = (const float4*)(sm + SM_LOS);
    const float4* __restrict__ hiE4 = (const float4*)(sm + SM_HIE);
    const float4* __restrict__ loE4 = (const float4*)(sm + SM_LOE);
    const float*  __restrict__ invt = sm + SM_INV;

    // register-block the E tile: read once, reuse across all 8 s
    float4 heR[8], leR[8];
    #pragma unroll
    for (int eg = 0; eg < 8; eg++) {
        int e = g * 8 + eg;
        heR[eg] = hiE4[e * 54 + c];
        leR[eg] = loE4[e * 54 + c];
    }

    float* base = out + ((size_t)(b * 65536 + s0 * 256 + e0 + g * 8)) * LL + c * 4;

    #pragma unroll 1
    for (int s = 0; s < 8; s++) {
        float4 hs = hiS4[s * 54 + c];
        float4 ls = loS4[s * 54 + c];
        float* ps = base + (size_t)s * (256 * LL);
        #pragma unroll
        for (int eg = 0; eg < 8; eg++) {
            float inv = invt[s * 32 + g * 8 + eg];
            float4 he = heR[eg];
            float4 le = leR[eg];
            float4 v;
            v.x = ((he.x - hs.x) + (le.x - ls.x)) * inv;
            v.y = ((he.y - hs.y) + (le.y - ls.y)) * inv;
            v.z = ((he.z - hs.z) + (le.z - ls.z)) * inv;
            v.w = ((he.w - hs.w) + (le.w - ls.w)) * inv;
            __stcs((float4*)(ps + eg * LL), v);   // streaming store: write-once output
        }
    }
}

extern "C" void kernel_launch(void* const* d_in, const int* in_sizes, int n_in,
                              void* d_out, int out_size) {
    const float* apc   = (const float*)d_in[0];
    const float* aroot = (const float*)d_in[1];
    const float* aqual = (const float*)d_in[2];
    // d_in[3] = inactive_pc: unused by the reference
    const float* iroot = (const float*)d_in[4];
    const float* iqual = (const float*)d_in[5];
    const float* hpc   = (const float*)d_in[6];
    const float* hroot = (const float*)d_in[7];
    const float* hqual = (const float*)d_in[8];
    const int*   pco   = (n_in > 9) ? (const int*)d_in[9] : nullptr;

    static bool attr_done = false;
    if (!attr_done) {
        cudaFuncSetAttribute(main_kernel, cudaFuncAttributeMaxDynamicSharedMemorySize,
                             SM_FLOATS * 4);
        attr_done = true;
    }

    prep_kernel<<<KK * BB + BB, 256>>>(apc, aroot, aqual, iroot, iqual,
                                       hpc, hroot, hqual, pco);
    d_kernel<<<dim3(TT + 1, BB), 224>>>();
    main_kernel<<<dim3(32, 8, BB), 256, SM_FLOATS * 4>>>((float*)d_out);
}

// round 13
// speedup vs baseline: 1.3849x; 1.0759x over previous
#include <cuda_runtime.h>
#include <cstdint>

#define BB 4
#define TT 256
#define LL 216
#define EPC 12
#define EROOT 12
#define EQUAL 16
#define KK 41
#define W_NM 0.1f
#define W_ADV 0.001f

// device scratch (no cudaMalloc allowed)
__device__ float g_cs[BB][TT + 1][48];                 // prefix sums, channel-innermost
__device__ float g_h[BB][KK][LL];                      // folded harmony coefficients, k-major
__device__ __align__(16) float g_Dhi[BB][TT + 1][LL];  // D = cs @ h, compensated hi
__device__ __align__(16) float g_Dlo[BB][TT + 1][LL];  // compensation (lo) part

// ---------------- K0a: prefix scans over t, one (b,channel) per block (R9 exact) ----------------
__global__ void prep_kernel(const float* __restrict__ apc,
                            const float* __restrict__ aroot,
                            const float* __restrict__ aqual,
                            const float* __restrict__ iroot,
                            const float* __restrict__ iqual) {
    __shared__ float wsum[8];
    int ch = blockIdx.x % KK;
    int b  = blockIdx.x / KK;
    int t  = threadIdx.x;
    int w  = t >> 5, lane = t & 31;
    float x;
    if (ch < 12) {
        x = apc[(b * TT + t) * EPC + ch];
    } else if (ch < 24) {
        int j = ch - 12;
        x = aroot[(b * TT + t) * EROOT + j] - W_ADV * iroot[(b * TT + t) * EROOT + j];
    } else if (ch < 40) {
        int j = ch - 24;
        x = aqual[(b * TT + t) * EQUAL + j] - W_ADV * iqual[(b * TT + t) * EQUAL + j];
    } else {
        x = 1.0f;  // channel 40 carries the -W_NM*Hs term (segment mean == 1)
    }
    float v = x;
    #pragma unroll
    for (int off = 1; off < 32; off <<= 1) {
        float n = __shfl_up_sync(0xFFFFFFFFu, v, off);
        if (lane >= off) v += n;
    }
    if (lane == 31) wsum[w] = v;
    __syncthreads();
    if (t < 8) {
        float s = wsum[t];
        #pragma unroll
        for (int off = 1; off < 8; off <<= 1) {
            float n = __shfl_up_sync(0x000000FFu, s, off);
            if (t >= off) s += n;
        }
        wsum[t] = s;
    }
    __syncthreads();
    float base = (w > 0) ? wsum[w - 1] : 0.0f;
    g_cs[b][t + 1][ch] = v + base;
    if (t == 0) g_cs[b][0][ch] = 0.0f;
}

// ---------------- K0b: h-fold, 4 blocks x 216 threads, writes g_h coalesced ----------------
__global__ void hfold_kernel(const float* __restrict__ hpc,
                             const float* __restrict__ hroot,
                             const float* __restrict__ hqual,
                             const int* __restrict__ pc_only) {
    int b = blockIdx.x;
    int l = threadIdx.x;
    if (l >= LL) return;
    int po = pc_only ? pc_only[0] : 0;
    float hv[12];
    float hs = 0.0f;
    #pragma unroll
    for (int j = 0; j < 12; j++) { hv[j] = hpc[(b * LL + l) * EPC + j]; hs += hv[j]; }
    float coef = (1.0f + 2.0f * W_NM) - W_ADV / hs;
    #pragma unroll
    for (int j = 0; j < 12; j++) g_h[b][j][l] = fmaf(hv[j], coef, -W_NM);
    #pragma unroll
    for (int j = 0; j < 12; j++) g_h[b][12 + j][l] = po ? 0.0f : hroot[(b * LL + l) * EROOT + j];
    #pragma unroll
    for (int j = 0; j < 16; j++) g_h[b][24 + j][l] = po ? 0.0f : hqual[(b * LL + l) * EQUAL + j];
    g_h[b][40][l] = -W_NM * hs;
}

// ---------------- K1: D = cs @ h (g_h coalesced), fp32 compensated accumulation ----------------
__global__ __launch_bounds__(224)
void d_kernel() {
    __shared__ float cs_s[KK];
    int t = blockIdx.x;   // 0..256
    int b = blockIdx.y;
    int l = threadIdx.x;  // 0..223
    if (l < KK) cs_s[l] = g_cs[b][t][l];
    __syncthreads();
    if (l >= LL) return;

    float s = 0.0f, c = 0.0f;
    #pragma unroll
    for (int k = 0; k < KK; k++) {
        float a  = cs_s[k];
        float h  = g_h[b][k][l];
        float p  = a * h;
        float ep = fmaf(a, h, -p);       // exact product error
        float tt = s + p;                // TwoSum
        float z  = tt - s;
        float e2 = (s - (tt - z)) + (p - z);
        s = tt;
        c += ep + e2;
    }
    g_Dhi[b][t][l] = s;
    g_Dlo[b][t][l] = c;
}

// ---------------- main: out[b,s,e,l] = (D[e+1,l]-D[s,l]) * inv_len ----------------
// R12 exact: E hi/lo register-blocked (loads once, reuse across 8 s); occ=2; __stcs stores.
// smem floats: hiS[8*216] | loS[8*216] | hiE[32*216] | loE[32*216] | inv[256]
#define SM_LOS 1728
#define SM_HIE 3456
#define SM_LOE 10368
#define SM_INV 17280
#define SM_FLOATS 17536   // 70144 bytes

__global__ __launch_bounds__(256, 2)
void main_kernel(float* __restrict__ out) {
    extern __shared__ float sm[];
    const int tid = threadIdx.x;
    const int st = blockIdx.x, et = blockIdx.y, b = blockIdx.z;
    const int s0 = st * 8, e0 = et * 32;

    const float* __restrict__ Dhi = &g_Dhi[b][0][0];
    const float* __restrict__ Dlo = &g_Dlo[b][0][0];

    // stage 40 D-rows (8 s-rows, 32 e-rows at t=e+1) as hi/lo
    for (int idx = tid; idx < 40 * 54; idx += 256) {
        int row = idx / 54, c = idx - row * 54;
        int t = (row < 8) ? (s0 + row) : (e0 + (row - 8) + 1);
        float4 vh = *(const float4*)(Dhi + t * LL + c * 4);
        float4 vl = *(const float4*)(Dlo + t * LL + c * 4);
        int dh = (row < 8) ? (row * LL) : (SM_HIE + (row - 8) * LL);
        int dl = dh + ((row < 8) ? SM_LOS : (SM_LOE - SM_HIE));
        *(float4*)(sm + dh + c * 4) = vh;
        *(float4*)(sm + dl + c * 4) = vl;
    }
    // inv table with validity baked in (inv = 0 for e < s)
    {
        int s = tid >> 5, e = tid & 31;
        int len = (e0 + e) - (s0 + s) + 1;
        sm[SM_INV + tid] = (len >= 1) ? __fdividef(1.0f, (float)len) : 0.0f;
    }
    __syncthreads();

    const int c = tid & 63;
    const int g = tid >> 6;
    if (c >= 54) return;

    const float4* __restrict__ hiS4 = (const float4*)sm;
    const float4* __restrict__ loS4 = (const float4*)(sm + SM_LOS);
    const float4* __restrict__ hiE4 = (const float4*)(sm + SM_HIE);
    const float4* __restrict__ loE4 = (const float4*)(sm + SM_LOE);
    const float*  __restrict__ invt = sm + SM_INV;

    // register-block the E tile: read once, reuse across all 8 s
    float4 heR[8], leR[8];
    #pragma unroll
    for (int eg = 0; eg < 8; eg++) {
        int e = g * 8 + eg;
        heR[eg] = hiE4[e * 54 + c];
        leR[eg] = loE4[e * 54 + c];
    }

    float* base = out + ((size_t)(b * 65536 + s0 * 256 + e0 + g * 8)) * LL + c * 4;

    #pragma unroll 1
    for (int s = 0; s < 8; s++) {
        float4 hs = hiS4[s * 54 + c];
        float4 ls = loS4[s * 54 + c];
        float* ps = base + (size_t)s * (256 * LL);
        #pragma unroll
        for (int eg = 0; eg < 8; eg++) {
            float inv = invt[s * 32 + g * 8 + eg];
            float4 he = heR[eg];
            float4 le = leR[eg];
            float4 v;
            v.x = ((he.x - hs.x) + (le.x - ls.x)) * inv;
            v.y = ((he.y - hs.y) + (le.y - ls.y)) * inv;
            v.z = ((he.z - hs.z) + (le.z - ls.z)) * inv;
            v.w = ((he.w - hs.w) + (le.w - ls.w)) * inv;
            __stcs((float4*)(ps + eg * LL), v);   // streaming store: write-once output
        }
    }
}

extern "C" void kernel_launch(void* const* d_in, const int* in_sizes, int n_in,
                              void* d_out, int out_size) {
    const float* apc   = (const float*)d_in[0];
    const float* aroot = (const float*)d_in[1];
    const float* aqual = (const float*)d_in[2];
    // d_in[3] = inactive_pc: unused by the reference
    const float* iroot = (const float*)d_in[4];
    const float* iqual = (const float*)d_in[5];
    const float* hpc   = (const float*)d_in[6];
    const float* hroot = (const float*)d_in[7];
    const float* hqual = (const float*)d_in[8];
    const int*   pco   = (n_in > 9) ? (const int*)d_in[9] : nullptr;

    static bool attr_done = false;
    if (!attr_done) {
        cudaFuncSetAttribute(main_kernel, cudaFuncAttributeMaxDynamicSharedMemorySize,
                             SM_FLOATS * 4);
        attr_done = true;
    }

    hfold_kernel<<<BB, 256>>>(hpc, hroot, hqual, pco);
    prep_kernel<<<KK * BB, 256>>>(apc, aroot, aqual, iroot, iqual);
    d_kernel<<<dim3(TT + 1, BB), 224>>>();
    main_kernel<<<dim3(32, 8, BB), 256, SM_FLOATS * 4>>>((float*)d_out);
}